// round 13
// baseline (speedup 1.0000x reference)
#include <cuda_runtime.h>

#define B_ 32
#define T_ 128
#define N_ 128
#define M_ 64
#define NT_ 192
#define NCTA 128

// ---------------- device scratch (no allocations allowed) ----------------
__device__ float g_V[B_ * N_ * N_];
__device__ float g_v[B_ * N_];
__device__ float g_w[B_ * N_];
__device__ float g_VF[B_ * N_ * NT_];
__device__ float g_Qxx[B_ * N_ * N_];
__device__ float g_Qu[B_ * M_ * NT_];   // rows 0..63: cols 0..127 = Qux, 128..191 = Quu
__device__ float g_qhat[B_ * NT_];
__device__ float g_K[(size_t)T_ * B_ * M_ * N_];
__device__ float g_k[T_ * B_ * M_];

// grid barrier state
__device__ unsigned g_barCnt = 0;
__device__ volatile unsigned g_barGen = 0;

__device__ __forceinline__ void grid_bar() {
    __syncthreads();
    if (threadIdx.x == 0) {
        unsigned gen = g_barGen;
        __threadfence();
        if (atomicAdd(&g_barCnt, 1u) == NCTA - 1u) {
            g_barCnt = 0;
            __threadfence();
            g_barGen = gen + 1u;
        } else {
            while (g_barGen == gen) { __nanosleep(64); }
        }
        __threadfence();   // acquire: invalidate L1D so other SMs' writes are seen
    }
    __syncthreads();
}

#define FMA16(a, bq)                                                                   \
    acc[0][0] += a.x * bq.x; acc[0][1] += a.x * bq.y; acc[0][2] += a.x * bq.z; acc[0][3] += a.x * bq.w; \
    acc[1][0] += a.y * bq.x; acc[1][1] += a.y * bq.y; acc[1][2] += a.y * bq.z; acc[1][3] += a.y * bq.w; \
    acc[2][0] += a.z * bq.x; acc[2][1] += a.z * bq.y; acc[2][2] += a.z * bq.z; acc[2][3] += a.z * bq.w; \
    acc[3][0] += a.w * bq.x; acc[3][1] += a.w * bq.y; acc[3][2] += a.w * bq.z; acc[3][3] += a.w * bq.w;

// ---------------- persistent backward kernel ----------------
__global__ __launch_bounds__(512) void kback(const float* __restrict__ A,
                                             const float* __restrict__ Bm,
                                             const float* __restrict__ c1,
                                             const float* __restrict__ Q,
                                             const float* __restrict__ p) {
    __shared__ __align__(16) float smem[8192];   // 32 KB, aliased per phase
    int cid = blockIdx.x, tid = threadIdx.x;

    // ---- phase 0: zero V, v ----
    for (int idx = cid * 512 + tid; idx < B_ * N_ * N_; idx += NCTA * 512) g_V[idx] = 0.0f;
    {
        int i = cid * 512 + tid;
        if (i < B_ * N_) g_v[i] = 0.0f;
    }
    grid_bar();

    for (int t = T_ - 1; t >= 0; t--) {
        // ================= phase 1: VF = V @ [A|B] ; w = V c + v =================
        if (cid < 96) {
            int b = cid / 3, part = cid % 3;
            size_t bt = (size_t)b * T_ + t;
            const float* Vb = g_V + b * N_ * N_;
            const float* Fsrc; int ldF, coff;
            if (part < 2) { Fsrc = A + bt * (size_t)(N_ * N_); ldF = 128; coff = part * 64; }
            else          { Fsrc = Bm + bt * (size_t)(N_ * M_); ldF = 64;  coff = 0; }
            float* Vs = smem;          // [16][128]
            float* Fs = smem + 2048;   // [16] stride 68
            int ty = tid >> 4, tx = tid & 15;
            float acc[4][4] = {};
            for (int kb = 0; kb < 128; kb += 16) {
                {
                    int mm = tid >> 5, r4 = tid & 31;   // V symmetric: stage rows kb+mm
                    *(float4*)&Vs[mm * 128 + r4 * 4] =
                        *(const float4*)(Vb + (kb + mm) * 128 + r4 * 4);
                }
                if (tid < 256) {
                    int mm = tid >> 4, c4 = tid & 15;
                    *(float4*)&Fs[mm * 68 + c4 * 4] =
                        *(const float4*)(Fsrc + (size_t)(kb + mm) * ldF + coff + c4 * 4);
                }
                __syncthreads();
#pragma unroll
                for (int kk = 0; kk < 16; kk++) {
                    float4 a = *(float4*)&Vs[kk * 128 + ty * 4];
                    float4 bq = *(float4*)&Fs[kk * 68 + tx * 4];
                    FMA16(a, bq)
                }
                __syncthreads();
            }
            float* outp = g_VF + b * N_ * NT_;
#pragma unroll
            for (int i = 0; i < 4; i++) {
                *(float4*)(outp + (ty * 4 + i) * NT_ + part * 64 + tx * 4) =
                    make_float4(acc[i][0], acc[i][1], acc[i][2], acc[i][3]);
            }
        } else {
            // w = V c + v
            int b = cid - 96;
            size_t bt = (size_t)b * T_ + t;
            float* cs = smem;
            if (tid < 128) cs[tid] = c1[bt * 128 + tid];
            __syncthreads();
            if (tid < 128) {
                const float* Vb = g_V + b * N_ * N_;
                float acc = g_v[b * 128 + tid];
#pragma unroll 8
                for (int m = 0; m < 128; m++) acc += Vb[m * 128 + tid] * cs[m];
                g_w[b * 128 + tid] = acc;
            }
            __syncthreads();
        }
        grid_bar();

        // ================= phase 2: Qhat tiles + qhat =================
        {
            float* As = smem;            // [16] stride 68
            float* Bs = smem + 1088;     // [16] stride 68
            float* outS = smem + 2176;   // [64][65]
            float* ws = smem + 6400;     // [128]
            int ty = tid >> 4, tx = tid & 15;

#pragma unroll 1
            for (int jj = 0; jj < 2; jj++) {
                int job = (jj == 0) ? cid : (cid < 64 ? 128 + cid : -1);
                if (job < 0) break;
                int b = job / 6, tile = job % 6;
                size_t bt = (size_t)b * T_ + t;
                bool isQxx = tile < 3;
                int ib, jb; const float* Asrc; int lda, aoff;
                if (isQxx) {
                    ib = (tile == 0) ? 0 : 64;
                    jb = (tile == 2) ? 64 : 0;
                    Asrc = A + bt * (size_t)(N_ * N_); lda = 128; aoff = ib;
                } else {
                    ib = 0; jb = (tile - 3) * 64;
                    Asrc = Bm + bt * (size_t)(N_ * M_); lda = 64; aoff = 0;
                }
                const float* VFb = g_VF + b * N_ * NT_;
                float acc[2][4] = {};
                for (int kb = 0; kb < 128; kb += 16) {
                    if (tid < 256) {
                        int mm = tid >> 4, c4 = tid & 15;
                        *(float4*)&As[mm * 68 + c4 * 4] =
                            *(const float4*)(Asrc + (size_t)(kb + mm) * lda + aoff + c4 * 4);
                    } else {
                        int t2 = tid - 256;
                        int mm = t2 >> 4, c4 = t2 & 15;
                        *(float4*)&Bs[mm * 68 + c4 * 4] =
                            *(const float4*)(VFb + (kb + mm) * NT_ + jb + c4 * 4);
                    }
                    __syncthreads();
#pragma unroll
                    for (int kk = 0; kk < 16; kk++) {
                        float a0 = As[kk * 68 + ty * 2];
                        float a1 = As[kk * 68 + ty * 2 + 1];
                        float4 b4 = *(float4*)&Bs[kk * 68 + tx * 4];
                        acc[0][0] += a0 * b4.x; acc[0][1] += a0 * b4.y;
                        acc[0][2] += a0 * b4.z; acc[0][3] += a0 * b4.w;
                        acc[1][0] += a1 * b4.x; acc[1][1] += a1 * b4.y;
                        acc[1][2] += a1 * b4.z; acc[1][3] += a1 * b4.w;
                    }
                    __syncthreads();
                }
                const float* Qb = Q + bt * (size_t)(NT_ * NT_);
                if (isQxx) {
                    float* outp = g_Qxx + b * N_ * N_;
#pragma unroll
                    for (int i = 0; i < 2; i++) {
                        int r = ib + ty * 2 + i, cc = jb + tx * 4;
                        float4 q4 = *(const float4*)(Qb + (size_t)r * NT_ + cc);
                        float4 o = make_float4(acc[i][0] + q4.x, acc[i][1] + q4.y,
                                               acc[i][2] + q4.z, acc[i][3] + q4.w);
                        *(float4*)(outp + r * N_ + cc) = o;
                        if (tile == 1) {
                            int rl = ty * 2 + i, cl = tx * 4;
                            outS[rl * 65 + cl]     = o.x;
                            outS[rl * 65 + cl + 1] = o.y;
                            outS[rl * 65 + cl + 2] = o.z;
                            outS[rl * 65 + cl + 3] = o.w;
                        }
                    }
                    if (tile == 1) {   // mirror (1,0) -> (0,1)
                        __syncthreads();
                        for (int idx = tid; idx < 64 * 64; idx += 512) {
                            int cl = idx >> 6, rl = idx & 63;
                            outp[cl * N_ + 64 + rl] = outS[rl * 65 + cl];
                        }
                        __syncthreads();
                    }
                } else {
                    float* outp = g_Qu + b * M_ * NT_;
#pragma unroll
                    for (int i = 0; i < 2; i++) {
                        int r = ty * 2 + i, cc = jb + tx * 4;
                        float4 q4 = *(const float4*)(Qb + (size_t)(128 + r) * NT_ + cc);
                        *(float4*)(outp + r * NT_ + cc) =
                            make_float4(acc[i][0] + q4.x, acc[i][1] + q4.y,
                                        acc[i][2] + q4.z, acc[i][3] + q4.w);
                    }
                }
            }

            if (cid >= 64 && cid < 96) {  // qhat = p + F^T w
                int b = cid - 64;
                size_t bt = (size_t)b * T_ + t;
                if (tid < 128) ws[tid] = g_w[b * 128 + tid];
                __syncthreads();
                if (tid < 192) {
                    float acc = p[bt * NT_ + tid];
                    if (tid < 128) {
                        const float* Ab = A + bt * (size_t)(N_ * N_);
#pragma unroll 4
                        for (int n = 0; n < 128; n++) acc += Ab[n * 128 + tid] * ws[n];
                    } else {
                        const float* Bb = Bm + bt * (size_t)(N_ * M_);
                        int j = tid - 128;
#pragma unroll 4
                        for (int n = 0; n < 128; n++) acc += Bb[n * 64 + j] * ws[n];
                    }
                    g_qhat[b * NT_ + tid] = acc;
                }
                __syncthreads();
            }
        }
        grid_bar();

        // ================= phase 3: Cholesky + solve + K/k + Vn + vn =================
        {
            float* sL = smem;             // [64] stride 68
            float* sPT = smem + 4352;     // [16] stride 68
            float* sRb = smem + 5440;     // [64] stride 36
            float* sInvD = smem + 7744;
            float* sk = smem + 7808;
            int b = cid >> 2, cg = cid & 3;
            int col0 = cg * 32;
            int ncols = (cg == 0) ? 33 : 32;
            const float* Qub = g_Qu + b * M_ * NT_;

            for (int idx = tid; idx < 64 * 16; idx += 512) {
                int i = idx >> 4, j4 = idx & 15;
                *(float4*)&sL[i * 68 + j4 * 4] = *(const float4*)(Qub + i * NT_ + 128 + j4 * 4);
            }
            for (int idx = tid; idx < 64 * 8; idx += 512) {
                int i = idx >> 3, c4 = idx & 7;
                *(float4*)&sRb[i * 36 + c4 * 4] = *(const float4*)(Qub + i * NT_ + col0 + c4 * 4);
            }
            if (cg == 0 && tid < 64) sRb[tid * 36 + 32] = g_qhat[b * NT_ + 128 + tid];
            __syncthreads();

            for (int kb = 0; kb < 64; kb += 16) {
                if (tid < 32) {
                    int l = tid & 15;
                    int row = kb + l;
                    float a[16];
#pragma unroll
                    for (int i = 0; i < 16; i++) a[i] = sL[row * 68 + kb + i];
#pragma unroll
                    for (int i = 0; i < 16; i++) {
                        float aii = __shfl_sync(0xffffffffu, a[i], i);
                        float dinv = rsqrtf(aii);
                        a[i] *= dinv;
                        if (tid == i) sInvD[kb + i] = dinv;
#pragma unroll
                        for (int c = i + 1; c < 16; c++) {
                            float lci = __shfl_sync(0xffffffffu, a[i], c);
                            a[c] -= a[i] * lci;
                        }
                    }
                    if (tid < 16) {
#pragma unroll
                        for (int i = 0; i < 16; i++)
                            if (i <= l) sL[row * 68 + kb + i] = a[i];
                    }
                }
                __syncthreads();

                int rem = 48 - kb;
                if (tid < rem) {
                    int r = kb + 16 + tid;
                    float a[16];
#pragma unroll
                    for (int i = 0; i < 16; i++) a[i] = sL[r * 68 + kb + i];
#pragma unroll
                    for (int i = 0; i < 16; i++) {
                        float s0 = 0.f, s1 = 0.f;
                        int m = 0;
#pragma unroll
                        for (; m + 1 < i; m += 2) {
                            s0 += a[m] * sL[(kb + i) * 68 + kb + m];
                            s1 += a[m + 1] * sL[(kb + i) * 68 + kb + m + 1];
                        }
                        if (m < i) s0 += a[m] * sL[(kb + i) * 68 + kb + m];
                        a[i] = (a[i] - s0 - s1) * sInvD[kb + i];
                    }
#pragma unroll
                    for (int i = 0; i < 16; i++) {
                        sL[r * 68 + kb + i] = a[i];
                        sPT[i * 68 + r] = a[i];
                    }
                } else if (tid >= 64 && tid < 64 + ncols) {
                    int c = tid - 64;
                    float yl[16];
#pragma unroll
                    for (int r = 0; r < 16; r++) yl[r] = sRb[(kb + r) * 36 + c];
#pragma unroll
                    for (int r = 0; r < 16; r++) {
                        float s0 = 0.f, s1 = 0.f;
                        int m = 0;
#pragma unroll
                        for (; m + 1 < r; m += 2) {
                            s0 += sL[(kb + r) * 68 + kb + m] * yl[m];
                            s1 += sL[(kb + r) * 68 + kb + m + 1] * yl[m + 1];
                        }
                        if (m < r) s0 += sL[(kb + r) * 68 + kb + m] * yl[m];
                        yl[r] = (yl[r] - s0 - s1) * sInvD[kb + r];
                        sRb[(kb + r) * 36 + c] = yl[r];
                    }
                }
                __syncthreads();

                if (rem > 0) {
                    if (tid < 384) {
                        int nstrip = rem * 16;
                        for (int idx = tid; idx < nstrip; idx += 384) {
                            int jr = kb + 16 + (idx >> 4);
                            int c4 = (idx & 15) * 4;
                            if (c4 >= kb + 16 && c4 <= jr) {
                                float4 s = *(float4*)&sL[jr * 68 + c4];
#pragma unroll
                                for (int m = 0; m < 16; m++) {
                                    float pj = sPT[m * 68 + jr];
                                    float4 pc = *(const float4*)&sPT[m * 68 + c4];
                                    s.x -= pj * pc.x; s.y -= pj * pc.y;
                                    s.z -= pj * pc.z; s.w -= pj * pc.w;
                                }
                                *(float4*)&sL[jr * 68 + c4] = s;
                            }
                        }
                    } else {
                        int slot = tid - 384;
                        int ng = rem >> 4;
                        if (slot < ncols * ng) {
                            int c = slot % ncols;
                            int g = slot / ncols;
                            int r0 = kb + 16 + g * 16;
                            float yv[16];
#pragma unroll
                            for (int m = 0; m < 16; m++) yv[m] = sRb[(kb + m) * 36 + c];
#pragma unroll
                            for (int r = 0; r < 16; r++) {
                                float s = sRb[(r0 + r) * 36 + c];
#pragma unroll
                                for (int m = 0; m < 16; m++)
                                    s -= sL[(r0 + r) * 68 + kb + m] * yv[m];
                                sRb[(r0 + r) * 36 + c] = s;
                            }
                        }
                    }
                    __syncthreads();
                }
            }

            // backward substitution
            for (int jb = 3; jb >= 0; jb--) {
                int base = jb * 16;
                if (tid < ncols) {
                    int c = tid;
                    float yl[16];
#pragma unroll
                    for (int r = 0; r < 16; r++) yl[r] = sRb[(base + r) * 36 + c];
#pragma unroll
                    for (int r = 15; r >= 0; r--) {
                        float s0 = 0.f, s1 = 0.f;
                        int m = r + 1;
#pragma unroll
                        for (; m + 1 < 16; m += 2) {
                            s0 += sL[(base + m) * 68 + base + r] * yl[m];
                            s1 += sL[(base + m + 1) * 68 + base + r] * yl[m + 1];
                        }
                        if (m < 16) s0 += sL[(base + m) * 68 + base + r] * yl[m];
                        yl[r] = (yl[r] - s0 - s1) * sInvD[base + r];
                        sRb[(base + r) * 36 + c] = yl[r];
                    }
                }
                __syncthreads();
                if (jb > 0 && tid < ncols * jb) {
                    int c = tid % ncols;
                    int g = tid / ncols;
                    int r0 = g * 16;
                    float yv[16];
#pragma unroll
                    for (int m = 0; m < 16; m++) yv[m] = sRb[(base + m) * 36 + c];
#pragma unroll
                    for (int r = 0; r < 16; r++) {
                        float s = sRb[(r0 + r) * 36 + c];
#pragma unroll
                        for (int m = 0; m < 16; m++)
                            s -= sL[(base + m) * 68 + (r0 + r)] * yv[m];
                        sRb[(r0 + r) * 36 + c] = s;
                    }
                }
                __syncthreads();
            }

            // store K slice; cg 0 stores k
            {
                float* Kb = g_K + ((size_t)t * B_ + b) * (M_ * N_);
                for (int idx = tid; idx < 64 * 32; idx += 512) {
                    int j = idx >> 5, cc = idx & 31;
                    Kb[j * 128 + col0 + cc] = -sRb[j * 36 + cc];
                }
                if (cg == 0 && tid < 64) {
                    float kv = -sRb[tid * 36 + 32];
                    g_k[((size_t)t * B_ + b) * M_ + tid] = kv;
                    sk[tid] = kv;
                }
            }
            __syncthreads();

            if (cg == 0 && tid < 128) {
                float acc = g_qhat[b * NT_ + tid];
#pragma unroll 8
                for (int m = 0; m < 64; m++) acc += Qub[m * NT_ + tid] * sk[m];
                g_v[b * 128 + tid] = acc;
            }

            // Vn slice
            {
                int tx2 = tid & 7;
                int ty2 = tid >> 3;
                float acc2[2][4] = {};
#pragma unroll 4
                for (int m = 0; m < 64; m++) {
                    float4 yv = *(const float4*)&sRb[m * 36 + tx2 * 4];
                    const float* qrow = Qub + m * NT_ + ty2 * 2;
                    float q0 = qrow[0], q1 = qrow[1];
                    acc2[0][0] += q0 * yv.x; acc2[0][1] += q0 * yv.y;
                    acc2[0][2] += q0 * yv.z; acc2[0][3] += q0 * yv.w;
                    acc2[1][0] += q1 * yv.x; acc2[1][1] += q1 * yv.y;
                    acc2[1][2] += q1 * yv.z; acc2[1][3] += q1 * yv.w;
                }
                const float* Qxxb = g_Qxx + b * N_ * N_;
                float* Vb = g_V + b * N_ * N_;
#pragma unroll
                for (int rr = 0; rr < 2; rr++) {
                    int i = ty2 * 2 + rr;
                    float4 q4 = *(const float4*)(Qxxb + i * N_ + col0 + tx2 * 4);
                    *(float4*)(Vb + i * N_ + col0 + tx2 * 4) =
                        make_float4(q4.x - acc2[rr][0], q4.y - acc2[rr][1],
                                    q4.z - acc2[rr][2], q4.w - acc2[rr][3]);
                }
            }
        }
        grid_bar();
    }
}

// ---------------- forward rollout ----------------
__global__ __launch_bounds__(256) void kfwd(const float* __restrict__ A,
                                            const float* __restrict__ Bm,
                                            const float* __restrict__ c1,
                                            const float* __restrict__ xinit,
                                            float* __restrict__ out) {
    int b = blockIdx.x, tid = threadIdx.x;
    int warp = tid >> 5, lane = tid & 31;
    __shared__ float sx[128], su[64], sxn[128];
    if (tid < 128) sx[tid] = xinit[b * 128 + tid];
    __syncthreads();

    for (int t = 0; t < 128; t++) {
        size_t bt = (size_t)b * T_ + t;
        const float* Kb = g_K + ((size_t)t * B_ + b) * (M_ * N_);
        const float* kb = g_k + ((size_t)t * B_ + b) * M_;
        for (int r = warp; r < 64; r += 8) {
            const float* kr = Kb + r * 128;
            float s = kr[lane] * sx[lane] + kr[32 + lane] * sx[32 + lane]
                    + kr[64 + lane] * sx[64 + lane] + kr[96 + lane] * sx[96 + lane];
#pragma unroll
            for (int o = 16; o; o >>= 1) s += __shfl_down_sync(0xffffffffu, s, o);
            if (lane == 0) su[r] = s + kb[r];
        }
        if (tid < 128) out[bt * NT_ + tid] = sx[tid];
        __syncthreads();
        if (tid < 64) out[bt * NT_ + 128 + tid] = su[tid];

        const float* Ab = A + bt * (size_t)(N_ * N_);
        const float* Bb = Bm + bt * (size_t)(N_ * M_);
        for (int r = warp; r < 128; r += 8) {
            const float* ar = Ab + r * 128;
            const float* br = Bb + r * 64;
            float s = ar[lane] * sx[lane] + ar[32 + lane] * sx[32 + lane]
                    + ar[64 + lane] * sx[64 + lane] + ar[96 + lane] * sx[96 + lane]
                    + br[lane] * su[lane] + br[32 + lane] * su[32 + lane];
#pragma unroll
            for (int o = 16; o; o >>= 1) s += __shfl_down_sync(0xffffffffu, s, o);
            if (lane == 0) sxn[r] = s + c1[bt * 128 + r];
        }
        __syncthreads();
        if (tid < 128) sx[tid] = sxn[tid];
        __syncthreads();
    }
}

// ---------------- launch ----------------
extern "C" void kernel_launch(void* const* d_in, const int* in_sizes, int n_in,
                              void* d_out, int out_size) {
    const float *A = 0, *Bm = 0, *c1 = 0, *Q = 0, *p = 0, *xinit = 0;
    for (int i = 0; i < n_in; i++) {
        switch (in_sizes[i]) {
            case 67108864:  A = (const float*)d_in[i]; break;      // 32*128*128*128
            case 33554432:  Bm = (const float*)d_in[i]; break;     // 32*128*128*64
            case 524288:    c1 = (const float*)d_in[i]; break;     // 32*128*128
            case 150994944: Q = (const float*)d_in[i]; break;      // 32*128*192*192
            case 786432:    p = (const float*)d_in[i]; break;      // 32*128*192
            case 4096:      xinit = (const float*)d_in[i]; break;  // 32*128
        }
    }
    float* out = (float*)d_out;

    kback<<<NCTA, 512>>>(A, Bm, c1, Q, p);
    kfwd<<<B_, 256>>>(A, Bm, c1, xinit, out);
}

// round 14
// speedup vs baseline: 1.1245x; 1.1245x over previous
#include <cuda_runtime.h>

#define B_ 32
#define T_ 128
#define N_ 128
#define M_ 64
#define NT_ 192

// ---------------- device scratch (no allocations allowed) ----------------
__device__ float g_V[B_ * N_ * N_];
__device__ float g_v[B_ * N_];
__device__ float g_w[B_ * N_];
__device__ float g_VF[B_ * N_ * NT_];
__device__ float g_Qxx[B_ * N_ * N_];
__device__ float g_Qu[B_ * M_ * NT_];   // rows 0..63: cols 0..127 = Qux, 128..191 = Quu
__device__ float g_qhat[B_ * NT_];
__device__ float g_K[(size_t)T_ * B_ * M_ * N_];
__device__ float g_k[T_ * B_ * M_];

#define FMA16(a, bq)                                                                   \
    acc[0][0] += a.x * bq.x; acc[0][1] += a.x * bq.y; acc[0][2] += a.x * bq.z; acc[0][3] += a.x * bq.w; \
    acc[1][0] += a.y * bq.x; acc[1][1] += a.y * bq.y; acc[1][2] += a.y * bq.z; acc[1][3] += a.y * bq.w; \
    acc[2][0] += a.z * bq.x; acc[2][1] += a.z * bq.y; acc[2][2] += a.z * bq.z; acc[2][3] += a.z * bq.w; \
    acc[3][0] += a.w * bq.x; acc[3][1] += a.w * bq.y; acc[3][2] += a.w * bq.z; acc[3][3] += a.w * bq.w;

// ---------------- init ----------------
__global__ void kzero() {
    int idx = blockIdx.x * 256 + threadIdx.x;
    if (idx < B_ * N_ * N_) g_V[idx] = 0.0f;
    if (idx < B_ * N_) g_v[idx] = 0.0f;
}

// ---------------- k1: VF = V @ [A|B] (128x64 tiles, V symmetric) ; w = V c + v ----------------
// grid (4, B_), 512 threads. part 0,1: A cols part*64; part 2: B; part 3: w.
__global__ __launch_bounds__(512) void k1_VF(const float* __restrict__ A,
                                             const float* __restrict__ Bm,
                                             const float* __restrict__ c1, int t) {
    __shared__ __align__(16) float Vs[16 * 128];
    __shared__ __align__(16) float Fs[16 * 68];
    int b = blockIdx.y, part = blockIdx.x, tid = threadIdx.x;
    const float* Vb = g_V + b * N_ * N_;
    size_t bt = (size_t)b * T_ + t;

    if (part == 3) {  // w = V c + v
        __shared__ float cs[128];
        if (tid < 128) cs[tid] = c1[bt * 128 + tid];
        __syncthreads();
        if (tid < 128) {
            float acc = g_v[b * 128 + tid];
#pragma unroll 8
            for (int m = 0; m < 128; m++) acc += Vb[m * 128 + tid] * cs[m];
            g_w[b * 128 + tid] = acc;
        }
        return;
    }

    const float* Fsrc; int ldF, coff;
    if (part < 2) { Fsrc = A + bt * (size_t)(N_ * N_); ldF = 128; coff = part * 64; }
    else          { Fsrc = Bm + bt * (size_t)(N_ * M_); ldF = 64;  coff = 0; }

    int ty = tid >> 4, tx = tid & 15;   // ty 0..31 (rows ty*4..+3), tx 0..15 (cols tx*4..+3)
    float acc[4][4] = {};

    for (int kb = 0; kb < 128; kb += 16) {
        {   // stage V rows kb..kb+15 (symmetric: V[k][r] = V[r][k])
            int mm = tid >> 5, r4 = tid & 31;
            *(float4*)&Vs[mm * 128 + r4 * 4] = *(const float4*)(Vb + (kb + mm) * 128 + r4 * 4);
        }
        if (tid < 256) {
            int mm = tid >> 4, c4 = tid & 15;
            *(float4*)&Fs[mm * 68 + c4 * 4] =
                *(const float4*)(Fsrc + (size_t)(kb + mm) * ldF + coff + c4 * 4);
        }
        __syncthreads();
#pragma unroll
        for (int kk = 0; kk < 16; kk++) {
            float4 a = *(float4*)&Vs[kk * 128 + ty * 4];
            float4 bq = *(float4*)&Fs[kk * 68 + tx * 4];
            FMA16(a, bq)
        }
        __syncthreads();
    }
    float* outp = g_VF + b * N_ * NT_;
#pragma unroll
    for (int i = 0; i < 4; i++) {
        *(float4*)(outp + (ty * 4 + i) * NT_ + part * 64 + tx * 4) =
            make_float4(acc[i][0], acc[i][1], acc[i][2], acc[i][3]);
    }
}

// ---------------- k2: Qhat, 4 jobs/batch, 512 threads ----------------
// j0: Qxx cols 0..63 (rows 0..127) + mirror lower half -> (0,1)
// j1: Qxx rows 64..127 cols 64..127  + qhat
// j2: Qu rows 0..63 cols 0..63
// j3: Qu rows 0..63 cols 64..191 (two 64-col groups)
__global__ __launch_bounds__(512) void k2_Qhat(const float* __restrict__ A,
                                               const float* __restrict__ Bm,
                                               const float* __restrict__ Q,
                                               const float* __restrict__ p, int t) {
    __shared__ __align__(16) float As[16 * 132];
    __shared__ __align__(16) float Bs[16 * 132];
    __shared__ float outS[64 * 65];
    int b = blockIdx.y, bx = blockIdx.x, tid = threadIdx.x;
    size_t bt = (size_t)b * T_ + t;
    const float* VFb = g_VF + b * N_ * NT_;
    const float* Qb = Q + bt * (size_t)(NT_ * NT_);
    const float* Ab = A + bt * (size_t)(N_ * N_);
    const float* Bb = Bm + bt * (size_t)(N_ * M_);

    if (bx == 0) {
        // ---- 128x64 tile: Qxx[:, 0:64] = Q + A^T VF[:, 0:64]; mirror lower half ----
        int ty = tid >> 4, tx = tid & 15;
        float acc[4][4] = {};
        for (int kb = 0; kb < 128; kb += 16) {
            {   // As[kk][r] = A[kb+kk][r], r 0..127
                int mm = tid >> 5, r4 = tid & 31;
                *(float4*)&As[mm * 132 + r4 * 4] = *(const float4*)(Ab + (kb + mm) * 128 + r4 * 4);
            }
            if (tid < 256) {
                int mm = tid >> 4, c4 = tid & 15;
                *(float4*)&Bs[mm * 132 + c4 * 4] = *(const float4*)(VFb + (kb + mm) * NT_ + c4 * 4);
            }
            __syncthreads();
#pragma unroll
            for (int kk = 0; kk < 16; kk++) {
                float4 a = *(float4*)&As[kk * 132 + ty * 4];
                float4 bq = *(float4*)&Bs[kk * 132 + tx * 4];
                FMA16(a, bq)
            }
            __syncthreads();
        }
        float* outp = g_Qxx + b * N_ * N_;
#pragma unroll
        for (int i = 0; i < 4; i++) {
            int r = ty * 4 + i, cc = tx * 4;
            float4 q4 = *(const float4*)(Qb + (size_t)r * NT_ + cc);
            float4 o = make_float4(acc[i][0] + q4.x, acc[i][1] + q4.y,
                                   acc[i][2] + q4.z, acc[i][3] + q4.w);
            *(float4*)(outp + r * N_ + cc) = o;
            if (r >= 64) {   // stash rows 64..127 for mirror
                int rl = r - 64;
                outS[rl * 65 + cc]     = o.x;
                outS[rl * 65 + cc + 1] = o.y;
                outS[rl * 65 + cc + 2] = o.z;
                outS[rl * 65 + cc + 3] = o.w;
            }
        }
        __syncthreads();
        for (int idx = tid; idx < 64 * 64; idx += 512) {
            int cl = idx >> 6, rl = idx & 63;
            outp[cl * N_ + 64 + rl] = outS[rl * 65 + cl];
        }
    } else if (bx == 1) {
        // ---- 64x64 tile: Qxx[64:,64:]; then qhat ----
        int ty = tid >> 4, tx = tid & 15;   // rows 64 + ty*2..+1, cols 64 + tx*4..+3
        float acc[2][4] = {};
        for (int kb = 0; kb < 128; kb += 16) {
            if (tid < 256) {
                int mm = tid >> 4, c4 = tid & 15;
                *(float4*)&As[mm * 132 + c4 * 4] =
                    *(const float4*)(Ab + (kb + mm) * 128 + 64 + c4 * 4);
            } else {
                int t2 = tid - 256;
                int mm = t2 >> 4, c4 = t2 & 15;
                *(float4*)&Bs[mm * 132 + c4 * 4] =
                    *(const float4*)(VFb + (kb + mm) * NT_ + 64 + c4 * 4);
            }
            __syncthreads();
#pragma unroll
            for (int kk = 0; kk < 16; kk++) {
                float a0 = As[kk * 132 + ty * 2];
                float a1 = As[kk * 132 + ty * 2 + 1];
                float4 b4 = *(float4*)&Bs[kk * 132 + tx * 4];
                acc[0][0] += a0 * b4.x; acc[0][1] += a0 * b4.y;
                acc[0][2] += a0 * b4.z; acc[0][3] += a0 * b4.w;
                acc[1][0] += a1 * b4.x; acc[1][1] += a1 * b4.y;
                acc[1][2] += a1 * b4.z; acc[1][3] += a1 * b4.w;
            }
            __syncthreads();
        }
        float* outp = g_Qxx + b * N_ * N_;
#pragma unroll
        for (int i = 0; i < 2; i++) {
            int r = 64 + ty * 2 + i, cc = 64 + tx * 4;
            float4 q4 = *(const float4*)(Qb + (size_t)r * NT_ + cc);
            *(float4*)(outp + r * N_ + cc) =
                make_float4(acc[i][0] + q4.x, acc[i][1] + q4.y,
                            acc[i][2] + q4.z, acc[i][3] + q4.w);
        }
        // qhat = p + F^T w
        __syncthreads();
        float* ws = outS;
        if (tid < 128) ws[tid] = g_w[b * 128 + tid];
        __syncthreads();
        if (tid < 192) {
            float acc1 = p[bt * NT_ + tid];
            if (tid < 128) {
#pragma unroll 4
                for (int n = 0; n < 128; n++) acc1 += Ab[n * 128 + tid] * ws[n];
            } else {
                int j = tid - 128;
#pragma unroll 4
                for (int n = 0; n < 128; n++) acc1 += Bb[n * 64 + j] * ws[n];
            }
            g_qhat[b * NT_ + tid] = acc1;
        }
    } else if (bx == 2) {
        // ---- 64x64 tile: Qu[:, 0:64] ----
        int ty = tid >> 4, tx = tid & 15;
        float acc[2][4] = {};
        for (int kb = 0; kb < 128; kb += 16) {
            if (tid < 256) {
                int mm = tid >> 4, c4 = tid & 15;
                *(float4*)&As[mm * 132 + c4 * 4] =
                    *(const float4*)(Bb + (size_t)(kb + mm) * 64 + c4 * 4);
            } else {
                int t2 = tid - 256;
                int mm = t2 >> 4, c4 = t2 & 15;
                *(float4*)&Bs[mm * 132 + c4 * 4] =
                    *(const float4*)(VFb + (kb + mm) * NT_ + c4 * 4);
            }
            __syncthreads();
#pragma unroll
            for (int kk = 0; kk < 16; kk++) {
                float a0 = As[kk * 132 + ty * 2];
                float a1 = As[kk * 132 + ty * 2 + 1];
                float4 b4 = *(float4*)&Bs[kk * 132 + tx * 4];
                acc[0][0] += a0 * b4.x; acc[0][1] += a0 * b4.y;
                acc[0][2] += a0 * b4.z; acc[0][3] += a0 * b4.w;
                acc[1][0] += a1 * b4.x; acc[1][1] += a1 * b4.y;
                acc[1][2] += a1 * b4.z; acc[1][3] += a1 * b4.w;
            }
            __syncthreads();
        }
        float* outp = g_Qu + b * M_ * NT_;
#pragma unroll
        for (int i = 0; i < 2; i++) {
            int r = ty * 2 + i, cc = tx * 4;
            float4 q4 = *(const float4*)(Qb + (size_t)(128 + r) * NT_ + cc);
            *(float4*)(outp + r * NT_ + cc) =
                make_float4(acc[i][0] + q4.x, acc[i][1] + q4.y,
                            acc[i][2] + q4.z, acc[i][3] + q4.w);
        }
    } else {
        // ---- 64x128 tile: Qu[:, 64:192] (two 64-col groups) ----
        int ty = tid >> 4, tx = tid & 15;
        float acc[2][4] = {};    // group A: cols 64 + tx*4
        float acc2[2][4] = {};   // group B: cols 128 + tx*4
        for (int kb = 0; kb < 128; kb += 16) {
            {   // stage VF cols 64..191 (16 x 128)
                int mm = tid >> 5, c4 = tid & 31;
                *(float4*)&Bs[mm * 132 + c4 * 4] =
                    *(const float4*)(VFb + (kb + mm) * NT_ + 64 + c4 * 4);
            }
            if (tid < 256) {
                int mm = tid >> 4, c4 = tid & 15;
                *(float4*)&As[mm * 132 + c4 * 4] =
                    *(const float4*)(Bb + (size_t)(kb + mm) * 64 + c4 * 4);
            }
            __syncthreads();
#pragma unroll
            for (int kk = 0; kk < 16; kk++) {
                float a0 = As[kk * 132 + ty * 2];
                float a1 = As[kk * 132 + ty * 2 + 1];
                float4 b4 = *(float4*)&Bs[kk * 132 + tx * 4];
                float4 c4v = *(float4*)&Bs[kk * 132 + 64 + tx * 4];
                acc[0][0] += a0 * b4.x; acc[0][1] += a0 * b4.y;
                acc[0][2] += a0 * b4.z; acc[0][3] += a0 * b4.w;
                acc[1][0] += a1 * b4.x; acc[1][1] += a1 * b4.y;
                acc[1][2] += a1 * b4.z; acc[1][3] += a1 * b4.w;
                acc2[0][0] += a0 * c4v.x; acc2[0][1] += a0 * c4v.y;
                acc2[0][2] += a0 * c4v.z; acc2[0][3] += a0 * c4v.w;
                acc2[1][0] += a1 * c4v.x; acc2[1][1] += a1 * c4v.y;
                acc2[1][2] += a1 * c4v.z; acc2[1][3] += a1 * c4v.w;
            }
            __syncthreads();
        }
        float* outp = g_Qu + b * M_ * NT_;
#pragma unroll
        for (int i = 0; i < 2; i++) {
            int r = ty * 2 + i;
            int ccA = 64 + tx * 4, ccB = 128 + tx * 4;
            float4 qA = *(const float4*)(Qb + (size_t)(128 + r) * NT_ + ccA);
            float4 qB = *(const float4*)(Qb + (size_t)(128 + r) * NT_ + ccB);
            *(float4*)(outp + r * NT_ + ccA) =
                make_float4(acc[i][0] + qA.x, acc[i][1] + qA.y,
                            acc[i][2] + qA.z, acc[i][3] + qA.w);
            *(float4*)(outp + r * NT_ + ccB) =
                make_float4(acc2[i][0] + qB.x, acc2[i][1] + qB.y,
                            acc2[i][2] + qB.z, acc2[i][3] + qB.w);
        }
    }
}

// ---------------- k3: Cholesky with FUSED forward substitution + backward + K/k + Vn + vn ----------------
// grid (4, B_), 512 threads. CTA cg handles Qux columns [cg*32, cg*32+32); cg==0 also qu.
__global__ __launch_bounds__(512) void k3_solve(int t) {
    __shared__ __align__(16) float sL[64 * 68];
    __shared__ __align__(16) float sPT[16 * 68];
    __shared__ __align__(16) float sRb[64 * 36];
    __shared__ float sInvD[64];
    __shared__ float sk[64];
    int b = blockIdx.y, cg = blockIdx.x, tid = threadIdx.x;
    int col0 = cg * 32;
    int ncols = (cg == 0) ? 33 : 32;   // local col 32 = qu (cg 0 only)
    const float* Qub = g_Qu + b * M_ * NT_;

    // stage Quu into sL and the RHS slice into sRb (float4, coalesced)
    for (int idx = tid; idx < 64 * 16; idx += 512) {
        int i = idx >> 4, j4 = idx & 15;
        *(float4*)&sL[i * 68 + j4 * 4] = *(const float4*)(Qub + i * NT_ + 128 + j4 * 4);
    }
    for (int idx = tid; idx < 64 * 8; idx += 512) {
        int i = idx >> 3, c4 = idx & 7;
        *(float4*)&sRb[i * 36 + c4 * 4] = *(const float4*)(Qub + i * NT_ + col0 + c4 * 4);
    }
    if (cg == 0 && tid < 64) sRb[tid * 36 + 32] = g_qhat[b * NT_ + 128 + tid];
    __syncthreads();

    // ---- blocked lower Cholesky with fused forward substitution ----
    for (int kb = 0; kb < 64; kb += 16) {
        // W1: factor 16x16 diagonal block in registers via shfl (warp 0)
        if (tid < 32) {
            int l = tid & 15;
            int row = kb + l;
            float a[16];
#pragma unroll
            for (int i = 0; i < 16; i++) a[i] = sL[row * 68 + kb + i];
#pragma unroll
            for (int i = 0; i < 16; i++) {
                float aii = __shfl_sync(0xffffffffu, a[i], i);
                float dinv = rsqrtf(aii);
                a[i] *= dinv;
                if (tid == i) sInvD[kb + i] = dinv;
#pragma unroll
                for (int c = i + 1; c < 16; c++) {
                    float lci = __shfl_sync(0xffffffffu, a[i], c);
                    a[c] -= a[i] * lci;
                }
            }
            if (tid < 16) {
#pragma unroll
                for (int i = 0; i < 16; i++)
                    if (i <= l) sL[row * 68 + kb + i] = a[i];
            }
        }
        __syncthreads();

        int rem = 48 - kb;
        // W2: chol panel solve (tid < rem)  ||  RHS diag-solve (tid in [64, 64+ncols))
        if (tid < rem) {
            int r = kb + 16 + tid;
            float a[16];
#pragma unroll
            for (int i = 0; i < 16; i++) a[i] = sL[r * 68 + kb + i];
#pragma unroll
            for (int i = 0; i < 16; i++) {
                float s0 = 0.f, s1 = 0.f;
                int m = 0;
#pragma unroll
                for (; m + 1 < i; m += 2) {
                    s0 += a[m] * sL[(kb + i) * 68 + kb + m];
                    s1 += a[m + 1] * sL[(kb + i) * 68 + kb + m + 1];
                }
                if (m < i) s0 += a[m] * sL[(kb + i) * 68 + kb + m];
                a[i] = (a[i] - s0 - s1) * sInvD[kb + i];
            }
#pragma unroll
            for (int i = 0; i < 16; i++) {
                sL[r * 68 + kb + i] = a[i];
                sPT[i * 68 + r] = a[i];
            }
        } else if (tid >= 64 && tid < 64 + ncols) {
            int c = tid - 64;
            float yl[16];
#pragma unroll
            for (int r = 0; r < 16; r++) yl[r] = sRb[(kb + r) * 36 + c];
#pragma unroll
            for (int r = 0; r < 16; r++) {
                float s0 = 0.f, s1 = 0.f;
                int m = 0;
#pragma unroll
                for (; m + 1 < r; m += 2) {
                    s0 += sL[(kb + r) * 68 + kb + m] * yl[m];
                    s1 += sL[(kb + r) * 68 + kb + m + 1] * yl[m + 1];
                }
                if (m < r) s0 += sL[(kb + r) * 68 + kb + m] * yl[m];
                yl[r] = (yl[r] - s0 - s1) * sInvD[kb + r];
                sRb[(kb + r) * 36 + c] = yl[r];
            }
        }
        __syncthreads();

        // W3: chol trailing strips (tid < 384) || RHS bulk elimination (tid >= 384)
        if (rem > 0) {
            if (tid < 384) {
                int nstrip = rem * 16;
                for (int idx = tid; idx < nstrip; idx += 384) {
                    int jr = kb + 16 + (idx >> 4);
                    int c4 = (idx & 15) * 4;
                    if (c4 >= kb + 16 && c4 <= jr) {
                        float4 s = *(float4*)&sL[jr * 68 + c4];
#pragma unroll
                        for (int m = 0; m < 16; m++) {
                            float pj = sPT[m * 68 + jr];
                            float4 pc = *(const float4*)&sPT[m * 68 + c4];
                            s.x -= pj * pc.x; s.y -= pj * pc.y;
                            s.z -= pj * pc.z; s.w -= pj * pc.w;
                        }
                        *(float4*)&sL[jr * 68 + c4] = s;
                    }
                }
            } else {
                int slot = tid - 384;
                int ng = rem >> 4;   // 3, 2, 1
                if (slot < ncols * ng) {
                    int c = slot % ncols;
                    int g = slot / ncols;
                    int r0 = kb + 16 + g * 16;
                    float yv[16];
#pragma unroll
                    for (int m = 0; m < 16; m++) yv[m] = sRb[(kb + m) * 36 + c];
#pragma unroll
                    for (int r = 0; r < 16; r++) {
                        float s = sRb[(r0 + r) * 36 + c];
#pragma unroll
                        for (int m = 0; m < 16; m++)
                            s -= sL[(r0 + r) * 68 + kb + m] * yv[m];
                        sRb[(r0 + r) * 36 + c] = s;
                    }
                }
            }
            __syncthreads();
        }
    }

    // ---- backward substitution: L^T x = y (L read transposed, broadcast) ----
    for (int jb = 3; jb >= 0; jb--) {
        int base = jb * 16;
        if (tid < ncols) {
            int c = tid;
            float yl[16];
#pragma unroll
            for (int r = 0; r < 16; r++) yl[r] = sRb[(base + r) * 36 + c];
#pragma unroll
            for (int r = 15; r >= 0; r--) {
                float s0 = 0.f, s1 = 0.f;
                int m = r + 1;
#pragma unroll
                for (; m + 1 < 16; m += 2) {
                    s0 += sL[(base + m) * 68 + base + r] * yl[m];
                    s1 += sL[(base + m + 1) * 68 + base + r] * yl[m + 1];
                }
                if (m < 16) s0 += sL[(base + m) * 68 + base + r] * yl[m];
                yl[r] = (yl[r] - s0 - s1) * sInvD[base + r];
                sRb[(base + r) * 36 + c] = yl[r];
            }
        }
        __syncthreads();
        if (jb > 0 && tid < ncols * jb) {
            int c = tid % ncols;
            int g = tid / ncols;
            int r0 = g * 16;
            float yv[16];
#pragma unroll
            for (int m = 0; m < 16; m++) yv[m] = sRb[(base + m) * 36 + c];
#pragma unroll
            for (int r = 0; r < 16; r++) {
                float s = sRb[(r0 + r) * 36 + c];
#pragma unroll
                for (int m = 0; m < 16; m++)
                    s -= sL[(base + m) * 68 + (r0 + r)] * yv[m];
                sRb[(r0 + r) * 36 + c] = s;
            }
        }
        __syncthreads();
    }

    // ---- store K slice; cg 0 stores k ----
    {
        float* Kb = g_K + ((size_t)t * B_ + b) * (M_ * N_);
        for (int idx = tid; idx < 64 * 32; idx += 512) {
            int j = idx >> 5, cc = idx & 31;
            Kb[j * 128 + col0 + cc] = -sRb[j * 36 + cc];
        }
        if (cg == 0 && tid < 64) {
            float kv = -sRb[tid * 36 + 32];
            g_k[((size_t)t * B_ + b) * M_ + tid] = kv;
            sk[tid] = kv;
        }
    }
    __syncthreads();

    // ---- vn = qx + Qux^T k (cg 0 only) ----
    if (cg == 0 && tid < 128) {
        float acc = g_qhat[b * NT_ + tid];
#pragma unroll 8
        for (int m = 0; m < 64; m++) acc += Qub[m * NT_ + tid] * sk[m];
        g_v[b * 128 + tid] = acc;
    }

    // ---- Vn slice: Vn[:, col0..col0+31] = Qxx[:, cols] - Qux^T @ y(slice) ----
    {
        int tx = tid & 7;         // col strip: cols col0 + tx*4 .. +3
        int ty = tid >> 3;        // 0..63 -> rows ty*2, ty*2+1
        float acc2[2][4] = {};
#pragma unroll 4
        for (int m = 0; m < 64; m++) {
            float4 yv = *(const float4*)&sRb[m * 36 + tx * 4];
            const float* qrow = Qub + m * NT_ + ty * 2;
            float q0 = qrow[0], q1 = qrow[1];
            acc2[0][0] += q0 * yv.x; acc2[0][1] += q0 * yv.y;
            acc2[0][2] += q0 * yv.z; acc2[0][3] += q0 * yv.w;
            acc2[1][0] += q1 * yv.x; acc2[1][1] += q1 * yv.y;
            acc2[1][2] += q1 * yv.z; acc2[1][3] += q1 * yv.w;
        }
        const float* Qxxb = g_Qxx + b * N_ * N_;
        float* Vb = g_V + b * N_ * N_;
#pragma unroll
        for (int rr = 0; rr < 2; rr++) {
            int i = ty * 2 + rr;
            float4 q4 = *(const float4*)(Qxxb + i * N_ + col0 + tx * 4);
            *(float4*)(Vb + i * N_ + col0 + tx * 4) =
                make_float4(q4.x - acc2[rr][0], q4.y - acc2[rr][1],
                            q4.z - acc2[rr][2], q4.w - acc2[rr][3]);
        }
    }
}

// ---------------- forward rollout ----------------
__global__ __launch_bounds__(256) void kfwd(const float* __restrict__ A,
                                            const float* __restrict__ Bm,
                                            const float* __restrict__ c1,
                                            const float* __restrict__ xinit,
                                            float* __restrict__ out) {
    int b = blockIdx.x, tid = threadIdx.x;
    int warp = tid >> 5, lane = tid & 31;
    __shared__ float sx[128], su[64], sxn[128];
    if (tid < 128) sx[tid] = xinit[b * 128 + tid];
    __syncthreads();

    for (int t = 0; t < 128; t++) {
        size_t bt = (size_t)b * T_ + t;
        const float* Kb = g_K + ((size_t)t * B_ + b) * (M_ * N_);
        const float* kb = g_k + ((size_t)t * B_ + b) * M_;
        for (int r = warp; r < 64; r += 8) {
            const float* kr = Kb + r * 128;
            float s = kr[lane] * sx[lane] + kr[32 + lane] * sx[32 + lane]
                    + kr[64 + lane] * sx[64 + lane] + kr[96 + lane] * sx[96 + lane];
#pragma unroll
            for (int o = 16; o; o >>= 1) s += __shfl_down_sync(0xffffffffu, s, o);
            if (lane == 0) su[r] = s + kb[r];
        }
        if (tid < 128) out[bt * NT_ + tid] = sx[tid];
        __syncthreads();
        if (tid < 64) out[bt * NT_ + 128 + tid] = su[tid];

        const float* Ab = A + bt * (size_t)(N_ * N_);
        const float* Bb = Bm + bt * (size_t)(N_ * M_);
        for (int r = warp; r < 128; r += 8) {
            const float* ar = Ab + r * 128;
            const float* br = Bb + r * 64;
            float s = ar[lane] * sx[lane] + ar[32 + lane] * sx[32 + lane]
                    + ar[64 + lane] * sx[64 + lane] + ar[96 + lane] * sx[96 + lane]
                    + br[lane] * su[lane] + br[32 + lane] * su[32 + lane];
#pragma unroll
            for (int o = 16; o; o >>= 1) s += __shfl_down_sync(0xffffffffu, s, o);
            if (lane == 0) sxn[r] = s + c1[bt * 128 + r];
        }
        __syncthreads();
        if (tid < 128) sx[tid] = sxn[tid];
        __syncthreads();
    }
}

// ---------------- launch ----------------
extern "C" void kernel_launch(void* const* d_in, const int* in_sizes, int n_in,
                              void* d_out, int out_size) {
    const float *A = 0, *Bm = 0, *c1 = 0, *Q = 0, *p = 0, *xinit = 0;
    for (int i = 0; i < n_in; i++) {
        switch (in_sizes[i]) {
            case 67108864:  A = (const float*)d_in[i]; break;      // 32*128*128*128
            case 33554432:  Bm = (const float*)d_in[i]; break;     // 32*128*128*64
            case 524288:    c1 = (const float*)d_in[i]; break;     // 32*128*128
            case 150994944: Q = (const float*)d_in[i]; break;      // 32*128*192*192
            case 786432:    p = (const float*)d_in[i]; break;      // 32*128*192
            case 4096:      xinit = (const float*)d_in[i]; break;  // 32*128
        }
    }
    float* out = (float*)d_out;

    kzero<<<(B_ * N_ * N_ + 255) / 256, 256>>>();
    for (int t = T_ - 1; t >= 0; t--) {
        k1_VF<<<dim3(4, B_), 512>>>(A, Bm, c1, t);
        k2_Qhat<<<dim3(4, B_), 512>>>(A, Bm, Q, p, t);
        k3_solve<<<dim3(4, B_), 512>>>(t);
    }
    kfwd<<<B_, 256>>>(A, Bm, c1, xinit, out);
}